// round 1
// baseline (speedup 1.0000x reference)
#include <cuda_runtime.h>

#define NN 200000
#define EE 400000
#define DD 64
#define BBATCH 16
#define NLVL 12
#define SCAN_NB ((NN + 1023) / 1024)   // 196

// ---------------- device scratch (no allocations allowed) ----------------
__device__ float g_h[NN * DD];          // node states
__device__ float g_agg[NN * DD];        // per-level gathered sums (indexed by node id)
__device__ int g_indeg[NN], g_outdeg[NN];
__device__ int g_in_ptr[NN + 1], g_out_ptr[NN + 1];
__device__ int g_cur_in[NN], g_cur_out[NN];
__device__ int g_csr_src[EE];           // in-edges grouped by dst
__device__ int g_csc_dst[EE];           // out-edges grouped by src
__device__ int g_fnodes[NN], g_bnodes[NN];
__device__ int g_fhist[NLVL], g_bhist[NLVL];
__device__ int g_foff[NLVL + 1], g_boff[NLVL + 1];
__device__ int g_fcur[NLVL], g_bcur[NLVL];
__device__ int g_bsum[2][SCAN_NB], g_bsum_s[2][SCAN_NB];

// ordered-uint encoding for atomic float max
__device__ __forceinline__ unsigned enc_f(float f) {
    unsigned u = __float_as_uint(f);
    return (u & 0x80000000u) ? ~u : (u | 0x80000000u);
}
__device__ __forceinline__ float dec_f(unsigned u) {
    return (u & 0x80000000u) ? __uint_as_float(u & 0x7FFFFFFFu)
                             : __uint_as_float(~u);
}

#define NEGMAX (-3.402823466e38f)

// ---------------- K1: init h, zero counters, init output ----------------
__global__ void k_init(const int* __restrict__ nt, const int* __restrict__ nip,
                       const float* __restrict__ Wenc, const float* __restrict__ benc,
                       float* __restrict__ out) {
    long long stride = (long long)gridDim.x * blockDim.x;
    for (long long idx = (long long)blockIdx.x * blockDim.x + threadIdx.x;
         idx < (long long)NN * DD; idx += stride) {
        int n = (int)(idx >> 6), d = (int)(idx & 63);
        g_h[idx] = (float)nt[n] * Wenc[d] + (float)nip[n] * Wenc[64 + d] + benc[d];
        if (idx < NN) { g_indeg[idx] = 0; g_outdeg[idx] = 0; }
        if (idx < NLVL) { g_fhist[idx] = 0; g_bhist[idx] = 0; }
        if (idx < BBATCH * 2 * DD) {
            int col = (int)(idx & 127);
            // max half gets enc(-FLT_MAX) = 0x00800000, sum half gets 0.0f
            ((unsigned*)out)[idx] = (col < 64) ? 0x00800000u : 0u;
        }
    }
}

// ---------------- K2: degrees + level histograms ----------------
__global__ void k_deg(const int* __restrict__ ei, const int* __restrict__ fl,
                      const int* __restrict__ bl) {
    int stride = gridDim.x * blockDim.x;
    for (int i = blockIdx.x * blockDim.x + threadIdx.x; i < EE; i += stride) {
        atomicAdd(&g_indeg[ei[EE + i]], 1);   // dst
        atomicAdd(&g_outdeg[ei[i]], 1);       // src
        if (i < NN) {
            atomicAdd(&g_fhist[fl[i]], 1);
            atomicAdd(&g_bhist[bl[i]], 1);
        }
    }
}

// ---------------- K3: block-local exclusive scans of indeg/outdeg ----------------
__global__ void k_scan1() {
    int which = blockIdx.x / SCAN_NB;   // 0 = indeg, 1 = outdeg
    int blk = blockIdx.x % SCAN_NB;
    const int* deg = which ? g_outdeg : g_indeg;
    int* ptr = which ? g_out_ptr : g_in_ptr;
    __shared__ int sh[256];
    int base = blk * 1024 + threadIdx.x * 4;
    int v[4];
    int s = 0;
#pragma unroll
    for (int j = 0; j < 4; j++) {
        int idx = base + j;
        v[j] = (idx < NN) ? deg[idx] : 0;
        s += v[j];
    }
    sh[threadIdx.x] = s;
    __syncthreads();
    for (int off = 1; off < 256; off <<= 1) {
        int t = 0;
        if (threadIdx.x >= off) t = sh[threadIdx.x - off];
        __syncthreads();
        sh[threadIdx.x] += t;
        __syncthreads();
    }
    int run = sh[threadIdx.x] - s;   // exclusive prefix within block
#pragma unroll
    for (int j = 0; j < 4; j++) {
        int idx = base + j;
        if (idx < NN) ptr[idx] = run;
        run += v[j];
    }
    if (threadIdx.x == 255) g_bsum[which][blk] = sh[255];
}

// ---------------- K4: tiny serial scans (block sums + level hists) ----------------
__global__ void k_scan2() {
    // single thread: 2*196 + 2*12 adds
    int t0 = 0;
    for (int i = 0; i < SCAN_NB; i++) { int t = g_bsum[0][i]; g_bsum_s[0][i] = t0; t0 += t; }
    int t1 = 0;
    for (int i = 0; i < SCAN_NB; i++) { int t = g_bsum[1][i]; g_bsum_s[1][i] = t1; t1 += t; }
    g_in_ptr[NN] = EE;
    g_out_ptr[NN] = EE;
    int a = 0;
    for (int l = 0; l < NLVL; l++) { g_foff[l] = a; g_fcur[l] = a; a += g_fhist[l]; }
    g_foff[NLVL] = a;
    a = 0;
    for (int l = 0; l < NLVL; l++) { g_boff[l] = a; g_bcur[l] = a; a += g_bhist[l]; }
    g_boff[NLVL] = a;
}

// ---------------- K5: add block offsets, init scatter cursors ----------------
__global__ void k_scan3() {
    int stride = gridDim.x * blockDim.x;
    for (int i = blockIdx.x * blockDim.x + threadIdx.x; i < 2 * NN; i += stride) {
        if (i < NN) {
            int v = g_in_ptr[i] + g_bsum_s[0][i >> 10];
            g_in_ptr[i] = v;
            g_cur_in[i] = v;
        } else {
            int j = i - NN;
            int v = g_out_ptr[j] + g_bsum_s[1][j >> 10];
            g_out_ptr[j] = v;
            g_cur_out[j] = v;
        }
    }
}

// ---------------- K6: scatter edges into CSR/CSC, nodes into level lists ----------------
__global__ void k_scatter(const int* __restrict__ ei, const int* __restrict__ fl,
                          const int* __restrict__ bl) {
    int stride = gridDim.x * blockDim.x;
    for (int i = blockIdx.x * blockDim.x + threadIdx.x; i < EE; i += stride) {
        int src = ei[i], dst = ei[EE + i];
        int p = atomicAdd(&g_cur_in[dst], 1);
        g_csr_src[p] = src;
        int q = atomicAdd(&g_cur_out[src], 1);
        g_csc_dst[q] = dst;
        if (i < NN) {
            int pf = atomicAdd(&g_fcur[fl[i]], 1);
            g_fnodes[pf] = i;
            int pb = atomicAdd(&g_bcur[bl[i]], 1);
            g_bnodes[pb] = i;
        }
    }
}

// ---------------- per-level gather: agg[v] = sum of h[nbr] ----------------
__global__ void k_gather(int level, int dir) {
    const int* off   = dir ? g_boff : g_foff;
    const int* nodes = dir ? g_bnodes : g_fnodes;
    const int* ptr   = dir ? g_out_ptr : g_in_ptr;
    const int* adj   = dir ? g_csc_dst : g_csr_src;
    int start = off[level];
    int cnt = off[level + 1] - start;
    int wid = (blockIdx.x * blockDim.x + threadIdx.x) >> 5;
    int lane = threadIdx.x & 31;
    int nwarps = (gridDim.x * blockDim.x) >> 5;
    for (int w = wid; w < cnt; w += nwarps) {
        int v = nodes[start + w];
        int e0 = ptr[v], e1 = ptr[v + 1];
        float2 acc = make_float2(0.f, 0.f);
        for (int e = e0; e < e1; e++) {
            int s = adj[e];
            float2 t = *((const float2*)(g_h + (size_t)s * DD) + lane);
            acc.x += t.x;
            acc.y += t.y;
        }
        *((float2*)(g_agg + (size_t)v * DD) + lane) = acc;
    }
}

// ---------------- per-level GEMM: h[v] = agg[v] @ W + deg(v)*b ----------------
__global__ void __launch_bounds__(256) k_gemm(int level, int dir,
                                              const float* __restrict__ W,
                                              const float* __restrict__ bias) {
    __shared__ float sW[64][64];
    __shared__ float sA[64][68];   // pad 4 -> 272B rows, 16B aligned
    __shared__ int sNode[64];
    __shared__ int sDeg[64];
    const int* off   = dir ? g_boff : g_foff;
    const int* nodes = dir ? g_bnodes : g_fnodes;
    const int* ptr   = dir ? g_out_ptr : g_in_ptr;
    int start = off[level];
    int cnt = off[level + 1] - start;
    int ntiles = (cnt + 63) >> 6;

    for (int i = threadIdx.x; i < 4096; i += 256) sW[i >> 6][i & 63] = W[i];

    int tx = threadIdx.x & 15, ty = threadIdx.x >> 4;
    int n0 = tx << 2, m0 = ty << 2;
    float4 bs = *(const float4*)(bias + n0);

    for (int tile = blockIdx.x; tile < ntiles; tile += gridDim.x) {
        // load A tile: thread -> row r, 16-float segment
        int r = threadIdx.x >> 2;
        int cseg = (threadIdx.x & 3) << 4;
        int m = tile * 64 + r;
        int v = -1, deg = 0;
        if (m < cnt) {
            v = nodes[start + m];
            deg = ptr[v + 1] - ptr[v];
        }
        if ((threadIdx.x & 3) == 0) { sNode[r] = v; sDeg[r] = deg; }
        const float4* src4 = (const float4*)(g_agg + (size_t)(v < 0 ? 0 : v) * DD + cseg);
#pragma unroll
        for (int i = 0; i < 4; i++) {
            float4 val = (v >= 0) ? src4[i] : make_float4(0.f, 0.f, 0.f, 0.f);
            *((float4*)&sA[r][cseg + i * 4]) = val;
        }
        __syncthreads();

        float c[4][4];
#pragma unroll
        for (int i = 0; i < 4; i++)
#pragma unroll
            for (int j = 0; j < 4; j++) c[i][j] = 0.f;

#pragma unroll 8
        for (int k = 0; k < 64; k++) {
            float4 b4 = *((const float4*)&sW[k][n0]);
            float a0 = sA[m0 + 0][k];
            float a1 = sA[m0 + 1][k];
            float a2 = sA[m0 + 2][k];
            float a3 = sA[m0 + 3][k];
            c[0][0] += a0 * b4.x; c[0][1] += a0 * b4.y; c[0][2] += a0 * b4.z; c[0][3] += a0 * b4.w;
            c[1][0] += a1 * b4.x; c[1][1] += a1 * b4.y; c[1][2] += a1 * b4.z; c[1][3] += a1 * b4.w;
            c[2][0] += a2 * b4.x; c[2][1] += a2 * b4.y; c[2][2] += a2 * b4.z; c[2][3] += a2 * b4.w;
            c[3][0] += a3 * b4.x; c[3][1] += a3 * b4.y; c[3][2] += a3 * b4.z; c[3][3] += a3 * b4.w;
        }

#pragma unroll
        for (int i = 0; i < 4; i++) {
            int v2 = sNode[m0 + i];
            if (v2 >= 0) {
                float dg = (float)sDeg[m0 + i];
                float4 o;
                o.x = c[i][0] + dg * bs.x;
                o.y = c[i][1] + dg * bs.y;
                o.z = c[i][2] + dg * bs.z;
                o.w = c[i][3] + dg * bs.w;
                *((float4*)(g_h + (size_t)v2 * DD + n0)) = o;
            }
        }
        __syncthreads();
    }
}

// ---------------- readout: masked max/sum pool per batch ----------------
__device__ __forceinline__ void pool_flush(int cb, float2 mx, float2 sm, int lane,
                                           float* out) {
    int d = 2 * lane;
    unsigned* uo = (unsigned*)out;
    atomicMax(&uo[cb * 128 + d], enc_f(mx.x));
    atomicMax(&uo[cb * 128 + d + 1], enc_f(mx.y));
    atomicAdd(&out[cb * 128 + 64 + d], sm.x);
    atomicAdd(&out[cb * 128 + 64 + d + 1], sm.y);
}

__global__ void k_pool(const int* __restrict__ nt, const int* __restrict__ batch,
                       float* __restrict__ out) {
    int chunk = (NN + gridDim.x - 1) / gridDim.x;
    int s = blockIdx.x * chunk;
    int e = min(NN, s + chunk);
    if (s >= e) return;
    int warp = threadIdx.x >> 5, lane = threadIdx.x & 31;
    int nw = blockDim.x >> 5;
    int len = e - s;
    int wchunk = (len + nw - 1) / nw;
    int ws = s + warp * wchunk;
    int we = min(e, ws + wchunk);
    float2 mx = make_float2(NEGMAX, NEGMAX);
    float2 sm = make_float2(0.f, 0.f);
    int cb = (ws < we) ? batch[ws] : -1;
    for (int n = ws; n < we; n++) {
        int bb = batch[n];
        if (bb != cb) {
            pool_flush(cb, mx, sm, lane, out);
            mx = make_float2(NEGMAX, NEGMAX);
            sm = make_float2(0.f, 0.f);
            cb = bb;
        }
        if (nt[n] == 1) {
            float2 v = *((const float2*)(g_h + (size_t)n * DD) + lane);
            mx.x = fmaxf(mx.x, v.x);
            mx.y = fmaxf(mx.y, v.y);
            sm.x += v.x;
            sm.y += v.y;
        }
    }
    if (cb >= 0) pool_flush(cb, mx, sm, lane, out);
}

// ---------------- decode ordered-uint max half ----------------
__global__ void k_fixup(float* __restrict__ out) {
    int i = threadIdx.x;           // 1024 = B*64
    int b = i >> 6, d = i & 63;
    int pos = b * 128 + d;
    unsigned u = ((unsigned*)out)[pos];
    out[pos] = dec_f(u);
}

// ---------------- launch ----------------
extern "C" void kernel_launch(void* const* d_in, const int* in_sizes, int n_in,
                              void* d_out, int out_size) {
    const int* nt    = (const int*)d_in[0];
    const int* nip   = (const int*)d_in[1];
    const int* ei    = (const int*)d_in[2];
    const int* fl    = (const int*)d_in[3];
    const int* bl    = (const int*)d_in[4];
    const int* batch = (const int*)d_in[5];
    const float* W_enc = (const float*)d_in[6];
    const float* b_enc = (const float*)d_in[7];
    const float* W_f   = (const float*)d_in[8];
    const float* b_f   = (const float*)d_in[9];
    const float* W_b   = (const float*)d_in[10];
    const float* b_b   = (const float*)d_in[11];
    float* out = (float*)d_out;

    k_init<<<2048, 256>>>(nt, nip, W_enc, b_enc, out);
    k_deg<<<1600, 256>>>(ei, fl, bl);
    k_scan1<<<2 * SCAN_NB, 256>>>();
    k_scan2<<<1, 1>>>();
    k_scan3<<<784, 256>>>();
    k_scatter<<<1600, 256>>>(ei, fl, bl);

    for (int l = 1; l < NLVL; l++) {
        k_gather<<<1480, 256>>>(l, 0);
        k_gemm<<<296, 256>>>(l, 0, W_f, b_f);
    }
    for (int l = 1; l < NLVL; l++) {
        k_gather<<<1480, 256>>>(l, 1);
        k_gemm<<<296, 256>>>(l, 1, W_b, b_b);
    }

    k_pool<<<592, 256>>>(nt, batch, out);
    k_fixup<<<1, 1024>>>(out);
}